// round 7
// baseline (speedup 1.0000x reference)
#include <cuda_runtime.h>
#include <cuda_bf16.h>
#include <math.h>
#include <cstdint>

// NT-Xent loss, N=4096, D=256, T=0.5, EPS=1e-8.
// loss = (S_d - 2N*S_p) / (2N)^2
//   S_p = (2/T) * sum_i dot(zn_i, zn_{i+N})          (fp32, from raw inputs)
//   S_d = sum_j [(2N-1)*log(rs_j) + log(max(rs_j-1,EPS))]
//   rs_j = sum_k exp(sim_jk/T); sim = zn@zn^T via FP8 e4m3 MMA on zn*16
//   (symmetric: lower-triangle tiles only; off-diag tiles emit row AND col sums)

#define NROWS 8192
#define NHALF 4096
#define DDIM  256
// acc = (16 zn)·(16 zn) = 256*sim; exp(sim/T)=exp(2 sim)=2^(acc * 2*log2(e)/256)
#define EXPC  0.011270273757f

__device__ unsigned char g_znb[NROWS * DDIM];   // e4m3 of zn*16
__device__ float         g_rs [NROWS];
__device__ float         g_sum_p;
__device__ double        g_sd;
__device__ int           g_ticket;

// ===================== PTX helpers ==========================================
__device__ __forceinline__ uint32_t smem_u32(const void* p) {
    uint32_t a;
    asm("{ .reg .u64 t; cvta.to.shared.u64 t, %1; cvt.u32.u64 %0, t; }" : "=r"(a) : "l"(p));
    return a;
}
#define CP_ASYNC16(sm, gp) \
    asm volatile("cp.async.cg.shared.global [%0], [%1], 16;" :: "r"(sm), "l"(gp))
#define CP_COMMIT() asm volatile("cp.async.commit_group;" ::: "memory")
#define CP_WAIT_1() asm volatile("cp.async.wait_group 1;" ::: "memory")
#define CP_WAIT_0() asm volatile("cp.async.wait_group 0;" ::: "memory")

#define LDSM_X4(r0, r1, r2, r3, addr) \
    asm volatile("ldmatrix.sync.aligned.m8n8.x4.shared.b16 {%0,%1,%2,%3}, [%4];" \
        : "=r"(r0), "=r"(r1), "=r"(r2), "=r"(r3) : "r"(addr))

#define MMA_FP8(d, a, b0, b1) \
    asm volatile("mma.sync.aligned.m16n8k32.row.col.f32.e4m3.e4m3.f32 " \
        "{%0,%1,%2,%3}, {%4,%5,%6,%7}, {%8,%9}, {%0,%1,%2,%3};" \
        : "+f"((d)[0]), "+f"((d)[1]), "+f"((d)[2]), "+f"((d)[3]) \
        : "r"((a)[0]), "r"((a)[1]), "r"((a)[2]), "r"((a)[3]), "r"(b0), "r"(b1))

__device__ __forceinline__ float ex2f(float x) {
    float y; asm("ex2.approx.f32 %0, %1;" : "=f"(y) : "f"(x)); return y;
}
__device__ __forceinline__ uint32_t f4_to_e4m3(float4 v) {
    uint16_t lo, hi;
    asm("cvt.rn.satfinite.e4m3x2.f32 %0, %1, %2;" : "=h"(lo) : "f"(v.y), "f"(v.x));
    asm("cvt.rn.satfinite.e4m3x2.f32 %0, %1, %2;" : "=h"(hi) : "f"(v.w), "f"(v.z));
    return (uint32_t)lo | ((uint32_t)hi << 16);
}

// ===================== Kernel 1: prep = normalize + positives ===============
// One warp per pair i: reads z_i and z_j rows, computes norms + pair dot,
// writes e4m3(zn*16) rows i and i+N, accumulates S_p. Also zeroes globals.
__global__ void __launch_bounds__(256) k_prep(const float* __restrict__ zi,
                                              const float* __restrict__ zj) {
    int gtid = blockIdx.x * 256 + threadIdx.x;
    if (gtid < NROWS) g_rs[gtid] = 0.0f;
    if (gtid == 0) { g_sum_p = 0.0f; g_sd = 0.0; g_ticket = 0; }

    int pair = gtid >> 5;
    int lane = threadIdx.x & 31;
    if (pair >= NHALF) return;

    const float4* a = (const float4*)(zi + (size_t)pair * DDIM);
    const float4* b = (const float4*)(zj + (size_t)pair * DDIM);
    float4 a0 = a[lane], a1 = a[lane + 32];
    float4 b0 = b[lane], b1 = b[lane + 32];

    float si = a0.x*a0.x + a0.y*a0.y + a0.z*a0.z + a0.w*a0.w
             + a1.x*a1.x + a1.y*a1.y + a1.z*a1.z + a1.w*a1.w;
    float sj = b0.x*b0.x + b0.y*b0.y + b0.z*b0.z + b0.w*b0.w
             + b1.x*b1.x + b1.y*b1.y + b1.z*b1.z + b1.w*b1.w;
    float dd = a0.x*b0.x + a0.y*b0.y + a0.z*b0.z + a0.w*b0.w
             + a1.x*b1.x + a1.y*b1.y + a1.z*b1.z + a1.w*b1.w;
    #pragma unroll
    for (int o = 16; o > 0; o >>= 1) {
        si += __shfl_xor_sync(0xffffffffu, si, o);
        sj += __shfl_xor_sync(0xffffffffu, sj, o);
        dd += __shfl_xor_sync(0xffffffffu, dd, o);
    }
    float invi = 1.0f / fmaxf(sqrtf(si), 1e-8f);
    float invj = 1.0f / fmaxf(sqrtf(sj), 1e-8f);

    if (lane == 0) atomicAdd(&g_sum_p, 4.0f * dd * invi * invj);  // 2/T = 4

    float ki = invi * 16.0f, kj = invj * 16.0f;
    uint32_t* ri = (uint32_t*)(g_znb + (size_t)pair * DDIM);
    uint32_t* rj = (uint32_t*)(g_znb + (size_t)(pair + NHALF) * DDIM);
    ri[lane]      = f4_to_e4m3(make_float4(a0.x*ki, a0.y*ki, a0.z*ki, a0.w*ki));
    ri[lane + 32] = f4_to_e4m3(make_float4(a1.x*ki, a1.y*ki, a1.z*ki, a1.w*ki));
    rj[lane]      = f4_to_e4m3(make_float4(b0.x*kj, b0.y*kj, b0.z*kj, b0.w*kj));
    rj[lane + 32] = f4_to_e4m3(make_float4(b1.x*kj, b1.y*kj, b1.z*kj, b1.w*kj));
}

// ===================== Kernel 2: FP8 sym sim-GEMM + exp + sums ==============
// Lower-triangle tiles: 64*65/2 = 2080 CTAs. 128x128 tile; 8 warps (2x4),
// warp tile 64x32. K=256 bytes in 2 stages of 128B; cp.async double buffer.
#define BM 128
#define BN 128
#define NSTAGE 2
#define NTB (NROWS / BM)
#define NTILES (NTB * (NTB + 1) / 2)

#define SMA      0
#define SMB      32768
#define SMROW    65536
#define SMCOL    66048
#define SM_TOTAL (66048 + 512)
#define STAGE_BYTES 16384

__global__ void __launch_bounds__(256) k_simexp() {
    extern __shared__ char smem[];
    float* srow = (float*)(smem + SMROW);
    float* scol = (float*)(smem + SMCOL);
    const uint32_t sb = smem_u32(smem);
    const int tid  = threadIdx.x;
    const int wid  = tid >> 5;
    const int lane = tid & 31;
    const int wr   = wid >> 2;
    const int wc   = wid & 3;

    int t  = blockIdx.x;
    int bi = (int)((sqrtf(8.0f * (float)t + 1.0f) - 1.0f) * 0.5f);
    while ((bi + 1) * (bi + 2) / 2 <= t) ++bi;
    while (bi * (bi + 1) / 2 > t)        --bi;
    int bj = t - bi * (bi + 1) / 2;
    const int rb   = bi * BM;
    const int cb   = bj * BN;
    const bool diag = (bi == bj);

    if (tid < BM) { srow[tid] = 0.0f; scol[tid] = 0.0f; }

    const unsigned char* Agp = g_znb + (size_t)rb * DDIM;
    const unsigned char* Bgp = g_znb + (size_t)cb * DDIM;

    // ldmatrix per-lane addressing (SMEM rows are 128B, SW8 chunk swizzle)
    const uint32_t rowAb = (uint32_t)(wr * 64 + (lane & 15)) * 128u;
    const uint32_t rowBb = (uint32_t)(wc * 32 + (lane & 7) + ((lane >> 4) << 3)) * 128u;
    const uint32_t swzA0 = (uint32_t)(lane >> 4);
    const uint32_t swzB0 = (uint32_t)((lane >> 3) & 1);
    const uint32_t lxor  = (uint32_t)(lane & 7);

    float acc[4][4][4];
    #pragma unroll
    for (int mt = 0; mt < 4; ++mt)
        #pragma unroll
        for (int nt = 0; nt < 4; ++nt)
            #pragma unroll
            for (int e = 0; e < 4; ++e) acc[mt][nt][e] = 0.0f;

    auto load_stage = [&](int s, int buf) {
        const int k0 = s * 128;            // byte offset in the 256B global row
        #pragma unroll
        for (int tt = 0; tt < 4; ++tt) {
            int idx = tid + tt * 256;      // 0..1023
            int r   = idx >> 3;            // 0..127
            int c   = idx & 7;             // 16B chunk
            uint32_t so = (uint32_t)r * 128u + (uint32_t)((c ^ (r & 7)) << 4);
            CP_ASYNC16(sb + SMA + buf * STAGE_BYTES + so, Agp + (size_t)r * DDIM + k0 + c * 16);
            if (!diag)
                CP_ASYNC16(sb + SMB + buf * STAGE_BYTES + so, Bgp + (size_t)r * DDIM + k0 + c * 16);
        }
        CP_COMMIT();
    };

    load_stage(0, 0);

    for (int s = 0; s < NSTAGE; ++s) {
        const int buf = s & 1;
        if (s + 1 < NSTAGE) { load_stage(s + 1, (s + 1) & 1); CP_WAIT_1(); }
        else                { CP_WAIT_0(); }
        __syncthreads();

        const uint32_t abase = sb + SMA + buf * STAGE_BYTES;
        const uint32_t bbase = diag ? abase : (sb + SMB + buf * STAGE_BYTES);

        #pragma unroll
        for (int ks = 0; ks < 4; ++ks) {   // 32 bytes (k32 fp8) per step
            uint32_t a[4][4];
            const uint32_t cA = (uint32_t)(ks * 2) + swzA0;
            const uint32_t aoff = abase + rowAb + ((cA ^ lxor) << 4);
            #pragma unroll
            for (int mt = 0; mt < 4; ++mt)
                LDSM_X4(a[mt][0], a[mt][1], a[mt][2], a[mt][3], aoff + mt * 2048);

            uint32_t b[2][4];
            const uint32_t cB = (uint32_t)(ks * 2) + swzB0;
            const uint32_t boff = bbase + rowBb + ((cB ^ lxor) << 4);
            #pragma unroll
            for (int bt = 0; bt < 2; ++bt)
                LDSM_X4(b[bt][0], b[bt][1], b[bt][2], b[bt][3], boff + bt * 2048);

            #pragma unroll
            for (int mt = 0; mt < 4; ++mt)
                #pragma unroll
                for (int nt = 0; nt < 4; ++nt)
                    MMA_FP8(acc[mt][nt], a[mt],
                            b[nt >> 1][(nt & 1) * 2], b[nt >> 1][(nt & 1) * 2 + 1]);
        }
        __syncthreads();
    }

    // ---- epilogue: exp(acc/256 * 2) via ex2; rows always, cols off-diag ----
    float csum0[4] = {0,0,0,0}, csum1[4] = {0,0,0,0};
    #pragma unroll
    for (int mt = 0; mt < 4; ++mt) {
        float slow = 0.0f, shigh = 0.0f;
        #pragma unroll
        for (int nt = 0; nt < 4; ++nt) {
            float e0 = ex2f(acc[mt][nt][0] * EXPC);
            float e1 = ex2f(acc[mt][nt][1] * EXPC);
            float e2 = ex2f(acc[mt][nt][2] * EXPC);
            float e3 = ex2f(acc[mt][nt][3] * EXPC);
            slow  += e0 + e1;
            shigh += e2 + e3;
            csum0[nt] += e0 + e2;
            csum1[nt] += e1 + e3;
        }
        #pragma unroll
        for (int o = 1; o < 4; o <<= 1) {
            slow  += __shfl_xor_sync(0xffffffffu, slow,  o);
            shigh += __shfl_xor_sync(0xffffffffu, shigh, o);
        }
        if ((lane & 3) == 0) {
            int r = wr * 64 + mt * 16 + (lane >> 2);
            atomicAdd(&srow[r],     slow);
            atomicAdd(&srow[r + 8], shigh);
        }
    }
    if (!diag) {
        #pragma unroll
        for (int nt = 0; nt < 4; ++nt) {
            #pragma unroll
            for (int o = 4; o < 32; o <<= 1) {
                csum0[nt] += __shfl_xor_sync(0xffffffffu, csum0[nt], o);
                csum1[nt] += __shfl_xor_sync(0xffffffffu, csum1[nt], o);
            }
            if (lane < 4) {
                int c = wc * 32 + nt * 8 + lane * 2;
                atomicAdd(&scol[c],     csum0[nt]);
                atomicAdd(&scol[c + 1], csum1[nt]);
            }
        }
    }
    __syncthreads();
    if (tid < BM) {
        atomicAdd(&g_rs[rb + tid], srow[tid]);
        if (!diag) atomicAdd(&g_rs[cb + tid], scol[tid]);
    }
}

// ===================== Kernel 3: S_d reduction + loss (ticket) ==============
#define SD_GRID 32
__global__ void __launch_bounds__(256) k_final(float* __restrict__ out) {
    __shared__ double red[256];
    __shared__ bool last;
    double s = 0.0;
    for (int r = blockIdx.x * 256 + threadIdx.x; r < NROWS; r += SD_GRID * 256) {
        float rs = g_rs[r];
        s += 8191.0 * (double)logf(rs) + (double)logf(fmaxf(rs - 1.0f, 1e-8f));
    }
    red[threadIdx.x] = s;
    __syncthreads();
    for (int o = 128; o > 0; o >>= 1) {
        if (threadIdx.x < o) red[threadIdx.x] += red[threadIdx.x + o];
        __syncthreads();
    }
    if (threadIdx.x == 0) {
        atomicAdd(&g_sd, red[0]);
        __threadfence();
        int old = atomicAdd(&g_ticket, 1);
        last = (old == SD_GRID - 1);
    }
    __syncthreads();
    if (last && threadIdx.x == 0) {
        double sd = atomicAdd(&g_sd, 0.0);   // atomic read (L2-coherent)
        double loss = (sd - 8192.0 * (double)g_sum_p) / (8192.0 * 8192.0);
        out[0] = (float)loss;
    }
}

// ===================== launch ===============================================
extern "C" void kernel_launch(void* const* d_in, const int* in_sizes, int n_in,
                              void* d_out, int out_size) {
    (void)in_sizes; (void)n_in; (void)out_size;
    const float* zi = (const float*)d_in[0];
    const float* zj = (const float*)d_in[1];
    float* out = (float*)d_out;

    cudaFuncSetAttribute(k_simexp, cudaFuncAttributeMaxDynamicSharedMemorySize, SM_TOTAL);

    k_prep<<<512, 256>>>(zi, zj);
    k_simexp<<<NTILES, 256, SM_TOTAL>>>();
    k_final<<<SD_GRID, 256>>>(out);
}

// round 8
// speedup vs baseline: 1.3993x; 1.3993x over previous
#include <cuda_runtime.h>
#include <cuda_bf16.h>
#include <math.h>
#include <cstdint>

// NT-Xent loss, N=4096, D=256, T=0.5, EPS=1e-8.
// loss = (S_d - 2N*S_p) / (2N)^2
//   S_p = (2/T) * sum_i dot(z_i, z_j)/(|z_i||z_j|)   (fp32, from raw inputs)
//   S_d = sum_j [(2N-1)*log(rs_j) + log(max(rs_j-1,EPS))]
//   rs_j = sum_k exp(sim_jk/T); sim = zn@zn^T        (bf16 HMMA, symmetric:
//   lower-triangle tiles only; off-diag tiles emit row AND col sums)

#define NROWS 8192
#define NHALF 4096
#define DDIM  256
#define LOG2E_X2 2.8853900817779268f   // exp(2s) = 2^(s*2*log2 e)

__device__ __nv_bfloat16 g_znb[NROWS * DDIM];   // bf16 normalized
__device__ float         g_rs [NROWS];
__device__ float         g_sum_p;
__device__ double        g_sd;
__device__ int           g_ticket;

// ===================== PTX helpers ==========================================
__device__ __forceinline__ uint32_t smem_u32(const void* p) {
    uint32_t a;
    asm("{ .reg .u64 t; cvta.to.shared.u64 t, %1; cvt.u32.u64 %0, t; }" : "=r"(a) : "l"(p));
    return a;
}
#define CP_ASYNC16(sm, gp) \
    asm volatile("cp.async.cg.shared.global [%0], [%1], 16;" :: "r"(sm), "l"(gp))
#define CP_COMMIT() asm volatile("cp.async.commit_group;" ::: "memory")
#define CP_WAIT_1() asm volatile("cp.async.wait_group 1;" ::: "memory")
#define CP_WAIT_0() asm volatile("cp.async.wait_group 0;" ::: "memory")

#define LDSM_X4(r0, r1, r2, r3, addr) \
    asm volatile("ldmatrix.sync.aligned.m8n8.x4.shared.b16 {%0,%1,%2,%3}, [%4];" \
        : "=r"(r0), "=r"(r1), "=r"(r2), "=r"(r3) : "r"(addr))

#define MMA16816(d, a, b0, b1) \
    asm volatile("mma.sync.aligned.m16n8k16.row.col.f32.bf16.bf16.f32 " \
        "{%0,%1,%2,%3}, {%4,%5,%6,%7}, {%8,%9}, {%0,%1,%2,%3};" \
        : "+f"((d)[0]), "+f"((d)[1]), "+f"((d)[2]), "+f"((d)[3]) \
        : "r"((a)[0]), "r"((a)[1]), "r"((a)[2]), "r"((a)[3]), "r"(b0), "r"(b1))

__device__ __forceinline__ float ex2f(float x) {
    float y; asm("ex2.approx.f32 %0, %1;" : "=f"(y) : "f"(x)); return y;
}

// ===================== Kernel 1: prep = normalize + positives ===============
// One warp per pair i: reads z_i and z_j rows, computes norms + pair dot,
// writes bf16 zn rows i and i+N, accumulates S_p. Also zeroes globals.
__global__ void __launch_bounds__(256) k_prep(const float* __restrict__ zi,
                                              const float* __restrict__ zj) {
    int gtid = blockIdx.x * 256 + threadIdx.x;
    if (gtid < NROWS) g_rs[gtid] = 0.0f;
    if (gtid == 0) { g_sum_p = 0.0f; g_sd = 0.0; g_ticket = 0; }

    int pair = gtid >> 5;
    int lane = threadIdx.x & 31;
    if (pair >= NHALF) return;

    const float4* a = (const float4*)(zi + (size_t)pair * DDIM);
    const float4* b = (const float4*)(zj + (size_t)pair * DDIM);
    float4 a0 = a[lane], a1 = a[lane + 32];
    float4 b0 = b[lane], b1 = b[lane + 32];

    float si = a0.x*a0.x + a0.y*a0.y + a0.z*a0.z + a0.w*a0.w
             + a1.x*a1.x + a1.y*a1.y + a1.z*a1.z + a1.w*a1.w;
    float sj = b0.x*b0.x + b0.y*b0.y + b0.z*b0.z + b0.w*b0.w
             + b1.x*b1.x + b1.y*b1.y + b1.z*b1.z + b1.w*b1.w;
    float dd = a0.x*b0.x + a0.y*b0.y + a0.z*b0.z + a0.w*b0.w
             + a1.x*b1.x + a1.y*b1.y + a1.z*b1.z + a1.w*b1.w;
    #pragma unroll
    for (int o = 16; o > 0; o >>= 1) {
        si += __shfl_xor_sync(0xffffffffu, si, o);
        sj += __shfl_xor_sync(0xffffffffu, sj, o);
        dd += __shfl_xor_sync(0xffffffffu, dd, o);
    }
    float invi = 1.0f / fmaxf(sqrtf(si), 1e-8f);
    float invj = 1.0f / fmaxf(sqrtf(sj), 1e-8f);

    if (lane == 0) atomicAdd(&g_sum_p, 4.0f * dd * invi * invj);  // 2/T = 4

    __nv_bfloat162* ri = (__nv_bfloat162*)(g_znb + (size_t)pair * DDIM);
    __nv_bfloat162* rj = (__nv_bfloat162*)(g_znb + (size_t)(pair + NHALF) * DDIM);
    ri[lane*2+0]      = __float22bfloat162_rn(make_float2(a0.x*invi, a0.y*invi));
    ri[lane*2+1]      = __float22bfloat162_rn(make_float2(a0.z*invi, a0.w*invi));
    ri[64+lane*2+0]   = __float22bfloat162_rn(make_float2(a1.x*invi, a1.y*invi));
    ri[64+lane*2+1]   = __float22bfloat162_rn(make_float2(a1.z*invi, a1.w*invi));
    rj[lane*2+0]      = __float22bfloat162_rn(make_float2(b0.x*invj, b0.y*invj));
    rj[lane*2+1]      = __float22bfloat162_rn(make_float2(b0.z*invj, b0.w*invj));
    rj[64+lane*2+0]   = __float22bfloat162_rn(make_float2(b1.x*invj, b1.y*invj));
    rj[64+lane*2+1]   = __float22bfloat162_rn(make_float2(b1.z*invj, b1.w*invj));
}

// ===================== Kernel 2: symmetric HMMA sim-GEMM + exp + sums =======
// Lower-triangle tiles only: 64*65/2 = 2080 CTAs. Tile (bi, bj), bj <= bi.
// 128x128 per CTA; 8 warps (2x4), warp tile 64x32; K=256, 4 stages of BK=64.
#define BM 128
#define BN 128
#define BK 64
#define NSTAGE 4
#define NTB (NROWS / BM)
#define NTILES (NTB * (NTB + 1) / 2)

#define SMA      0
#define SMB      32768
#define SMROW    65536
#define SMCOL    66048
#define SM_TOTAL (66048 + 512)
#define STAGE_BYTES 16384

__global__ void __launch_bounds__(256) k_simexp() {
    extern __shared__ char smem[];
    float* srow = (float*)(smem + SMROW);
    float* scol = (float*)(smem + SMCOL);
    const uint32_t sb = smem_u32(smem);
    const int tid  = threadIdx.x;
    const int wid  = tid >> 5;
    const int lane = tid & 31;
    const int wr   = wid >> 2;
    const int wc   = wid & 3;

    // decode lower-triangle tile index: t = bi*(bi+1)/2 + bj, bj <= bi
    int t  = blockIdx.x;
    int bi = (int)((sqrtf(8.0f * (float)t + 1.0f) - 1.0f) * 0.5f);
    while ((bi + 1) * (bi + 2) / 2 <= t) ++bi;
    while (bi * (bi + 1) / 2 > t)        --bi;
    int bj = t - bi * (bi + 1) / 2;
    const int rb   = bi * BM;
    const int cb   = bj * BN;
    const bool diag = (bi == bj);

    if (tid < BM) { srow[tid] = 0.0f; scol[tid] = 0.0f; }

    const __nv_bfloat16* Agp = g_znb + (size_t)rb * DDIM;
    const __nv_bfloat16* Bgp = g_znb + (size_t)cb * DDIM;

    const uint32_t rowAb = (uint32_t)(wr * 64 + (lane & 15)) * 128u;
    const uint32_t rowBb = (uint32_t)(wc * 32 + (lane & 7) + ((lane >> 4) << 3)) * 128u;
    const uint32_t swzA0 = (uint32_t)(lane >> 4);
    const uint32_t swzB0 = (uint32_t)((lane >> 3) & 1);
    const uint32_t lxor  = (uint32_t)(lane & 7);

    float acc[4][4][4];
    #pragma unroll
    for (int mt = 0; mt < 4; ++mt)
        #pragma unroll
        for (int nt = 0; nt < 4; ++nt)
            #pragma unroll
            for (int e = 0; e < 4; ++e) acc[mt][nt][e] = 0.0f;

    auto load_stage = [&](int s, int buf) {
        const int k0 = s * BK;
        #pragma unroll
        for (int tt = 0; tt < 4; ++tt) {
            int idx = tid + tt * 256;
            int r   = idx >> 3;
            int c   = idx & 7;
            uint32_t so = (uint32_t)r * 128u + (uint32_t)((c ^ (r & 7)) << 4);
            CP_ASYNC16(sb + SMA + buf * STAGE_BYTES + so, Agp + (size_t)r * DDIM + k0 + c * 8);
            if (!diag)
                CP_ASYNC16(sb + SMB + buf * STAGE_BYTES + so, Bgp + (size_t)r * DDIM + k0 + c * 8);
        }
        CP_COMMIT();
    };

    load_stage(0, 0);

    for (int s = 0; s < NSTAGE; ++s) {
        const int buf = s & 1;
        if (s + 1 < NSTAGE) { load_stage(s + 1, (s + 1) & 1); CP_WAIT_1(); }
        else                { CP_WAIT_0(); }
        __syncthreads();

        const uint32_t abase = sb + SMA + buf * STAGE_BYTES;
        const uint32_t bbase = diag ? abase : (sb + SMB + buf * STAGE_BYTES);

        #pragma unroll
        for (int ks = 0; ks < 4; ++ks) {
            uint32_t a[4][4];
            const uint32_t cA = (uint32_t)(ks * 2) + swzA0;
            const uint32_t aoff = abase + rowAb + ((cA ^ lxor) << 4);
            #pragma unroll
            for (int mt = 0; mt < 4; ++mt)
                LDSM_X4(a[mt][0], a[mt][1], a[mt][2], a[mt][3], aoff + mt * 2048);

            uint32_t b[2][4];
            const uint32_t cB = (uint32_t)(ks * 2) + swzB0;
            const uint32_t boff = bbase + rowBb + ((cB ^ lxor) << 4);
            #pragma unroll
            for (int bt = 0; bt < 2; ++bt)
                LDSM_X4(b[bt][0], b[bt][1], b[bt][2], b[bt][3], boff + bt * 2048);

            #pragma unroll
            for (int mt = 0; mt < 4; ++mt)
                #pragma unroll
                for (int nt = 0; nt < 4; ++nt)
                    MMA16816(acc[mt][nt], a[mt],
                             b[nt >> 1][(nt & 1) * 2], b[nt >> 1][(nt & 1) * 2 + 1]);
        }
        __syncthreads();
    }

    // ---- epilogue: exp(2*sim); rows always; cols when off-diagonal ---------
    float csum0[4] = {0,0,0,0}, csum1[4] = {0,0,0,0};
    #pragma unroll
    for (int mt = 0; mt < 4; ++mt) {
        float slow = 0.0f, shigh = 0.0f;
        #pragma unroll
        for (int nt = 0; nt < 4; ++nt) {
            float e0 = ex2f(acc[mt][nt][0] * LOG2E_X2);
            float e1 = ex2f(acc[mt][nt][1] * LOG2E_X2);
            float e2 = ex2f(acc[mt][nt][2] * LOG2E_X2);
            float e3 = ex2f(acc[mt][nt][3] * LOG2E_X2);
            slow  += e0 + e1;
            shigh += e2 + e3;
            csum0[nt] += e0 + e2;
            csum1[nt] += e1 + e3;
        }
        #pragma unroll
        for (int o = 1; o < 4; o <<= 1) {
            slow  += __shfl_xor_sync(0xffffffffu, slow,  o);
            shigh += __shfl_xor_sync(0xffffffffu, shigh, o);
        }
        if ((lane & 3) == 0) {
            int r = wr * 64 + mt * 16 + (lane >> 2);
            atomicAdd(&srow[r],     slow);
            atomicAdd(&srow[r + 8], shigh);
        }
    }
    if (!diag) {
        #pragma unroll
        for (int nt = 0; nt < 4; ++nt) {
            #pragma unroll
            for (int o = 4; o < 32; o <<= 1) {
                csum0[nt] += __shfl_xor_sync(0xffffffffu, csum0[nt], o);
                csum1[nt] += __shfl_xor_sync(0xffffffffu, csum1[nt], o);
            }
            if (lane < 4) {
                int c = wc * 32 + nt * 8 + lane * 2;
                atomicAdd(&scol[c],     csum0[nt]);
                atomicAdd(&scol[c + 1], csum1[nt]);
            }
        }
    }
    __syncthreads();
    if (tid < BM) {
        atomicAdd(&g_rs[rb + tid], srow[tid]);
        if (!diag) atomicAdd(&g_rs[cb + tid], scol[tid]);
    }
}

// ===================== Kernel 3: S_d reduction + loss (ticket) ==============
#define SD_GRID 32
__global__ void __launch_bounds__(256) k_final(float* __restrict__ out) {
    __shared__ double red[256];
    __shared__ bool last;
    double s = 0.0;
    for (int r = blockIdx.x * 256 + threadIdx.x; r < NROWS; r += SD_GRID * 256) {
        float rs = g_rs[r];
        s += 8191.0 * (double)logf(rs) + (double)logf(fmaxf(rs - 1.0f, 1e-8f));
    }
    red[threadIdx.x] = s;
    __syncthreads();
    for (int o = 128; o > 0; o >>= 1) {
        if (threadIdx.x < o) red[threadIdx.x] += red[threadIdx.x + o];
        __syncthreads();
    }
    if (threadIdx.x == 0) {
        atomicAdd(&g_sd, red[0]);
        __threadfence();
        int old = atomicAdd(&g_ticket, 1);
        last = (old == SD_GRID - 1);
    }
    __syncthreads();
    if (last && threadIdx.x == 0) {
        double sd = atomicAdd(&g_sd, 0.0);   // atomic read (coherent)
        double loss = (sd - 8192.0 * (double)g_sum_p) / (8192.0 * 8192.0);
        out[0] = (float)loss;
    }
}

// ===================== launch ===============================================
extern "C" void kernel_launch(void* const* d_in, const int* in_sizes, int n_in,
                              void* d_out, int out_size) {
    (void)in_sizes; (void)n_in; (void)out_size;
    const float* zi = (const float*)d_in[0];
    const float* zj = (const float*)d_in[1];
    float* out = (float*)d_out;

    cudaFuncSetAttribute(k_simexp, cudaFuncAttributeMaxDynamicSharedMemorySize, SM_TOTAL);

    k_prep<<<512, 256>>>(zi, zj);
    k_simexp<<<NTILES, 256, SM_TOTAL>>>();
    k_final<<<SD_GRID, 256>>>(out);
}